// round 2
// baseline (speedup 1.0000x reference)
#include <cuda_runtime.h>
#include <cuda_fp16.h>
#include <cstdint>

// Paged KV-cache GQA decode attention, fp16 tensor-core flash-attention.
// Shapes (fixed by the problem):
//   q:  [8, 32, 128, 128] f32      storage_k/v: [8, 8, 64, 128, 128] f32
//   block_table: [8, 32] i32       ctx_len: [8] i32
//   out: [8, 32, 128, 128] f32
// Mask reduces to k_pos < ctx_len[b] (causal term is implied), so this is
// plain shared-length flash attention per batch.

namespace {

constexpr int kB    = 8;
constexpr int kHQ   = 32;
constexpr int kTQ   = 128;
constexpr int kD    = 128;
constexpr int kHKV  = 8;
constexpr int kMAXB = 64;
constexpr int kBS   = 128;
constexpr int kNB   = 32;
constexpr int kRep  = kHQ / kHKV;
constexpr float kCexp = 0.12751879523435302f;  // (1/sqrt(128)) * log2(e)
constexpr int kStride = 136;                   // halfwords per smem row (pad vs 128)
constexpr int kTileHalfs = 128 * kStride;
constexpr int kSmemBytes = 2 * kTileHalfs * 2; // K tile + V tile, fp16

__device__ __forceinline__ float fexp2(float x) {
    float r;
    asm("ex2.approx.ftz.f32 %0, %1;" : "=f"(r) : "f"(x));
    return r;
}

__device__ __forceinline__ uint32_t s2u(const void* p) {
    return (uint32_t)__cvta_generic_to_shared(p);
}

__device__ __forceinline__ void ldsm4(uint32_t a, uint32_t& r0, uint32_t& r1,
                                      uint32_t& r2, uint32_t& r3) {
    asm volatile("ldmatrix.sync.aligned.m8n8.x4.shared.b16 {%0,%1,%2,%3}, [%4];"
                 : "=r"(r0), "=r"(r1), "=r"(r2), "=r"(r3) : "r"(a));
}
__device__ __forceinline__ void ldsm4t(uint32_t a, uint32_t& r0, uint32_t& r1,
                                       uint32_t& r2, uint32_t& r3) {
    asm volatile("ldmatrix.sync.aligned.m8n8.x4.trans.shared.b16 {%0,%1,%2,%3}, [%4];"
                 : "=r"(r0), "=r"(r1), "=r"(r2), "=r"(r3) : "r"(a));
}
__device__ __forceinline__ void mma16816(float* c, uint32_t a0, uint32_t a1,
                                         uint32_t a2, uint32_t a3,
                                         uint32_t b0, uint32_t b1) {
    asm volatile(
        "mma.sync.aligned.m16n8k16.row.col.f32.f16.f16.f32 "
        "{%0,%1,%2,%3}, {%4,%5,%6,%7}, {%8,%9}, {%0,%1,%2,%3};"
        : "+f"(c[0]), "+f"(c[1]), "+f"(c[2]), "+f"(c[3])
        : "r"(a0), "r"(a1), "r"(a2), "r"(a3), "r"(b0), "r"(b1));
}
__device__ __forceinline__ uint32_t packh2(float x, float y) {
    __half2 h = __floats2half2_rn(x, y);
    return *reinterpret_cast<uint32_t*>(&h);
}

__global__ void __launch_bounds__(256, 1)
attn_kernel(const float* __restrict__ q, const float* __restrict__ sk,
            const float* __restrict__ sv, const int* __restrict__ bt,
            const int* __restrict__ cl, float* __restrict__ out)
{
    extern __shared__ __half smem[];
    __half* Ks = smem;                 // K tile; also used to stage Q
    __half* Vs = smem + kTileHalfs;    // V tile

    const int hq  = blockIdx.x;
    const int b   = blockIdx.y;
    const int hkv = hq / kRep;
    const int tid = threadIdx.x;
    const int warp = tid >> 5;
    const int lane = tid & 31;

    float* outBase = out + (size_t)(b * kHQ + hq) * kTQ * kD;
    const int n = cl[b];
    if (n <= 0) {
        float4 z = make_float4(0.f, 0.f, 0.f, 0.f);
        for (int i = tid; i < kTQ * kD / 4; i += 256)
            reinterpret_cast<float4*>(outBase)[i] = z;
        return;
    }

    // ---- stage Q (f32 -> f16) into smem, then pull A-fragments ----
    const float* qBase = q + (size_t)(b * kHQ + hq) * kTQ * kD;
    {
        const int r = tid >> 1, c = (tid & 1) * 64;
        #pragma unroll
        for (int i = 0; i < 16; ++i) {
            float4 f = *reinterpret_cast<const float4*>(qBase + r * kD + c + i * 4);
            *reinterpret_cast<uint2*>(&Ks[r * kStride + c + i * 4]) =
                make_uint2(packh2(f.x, f.y), packh2(f.z, f.w));
        }
    }
    __syncthreads();

    const int within = lane & 7;
    const int g8 = lane >> 3;
    // ldmatrix lane->address patterns:
    //   A-pattern (Q frags, V-trans B frags): row +8 if g8&1, col +8 if g8&2
    //   K B-pattern: col +8 if g8&1, row +8 if g8&2
    const int rowA = within + ((g8 & 1) << 3);
    const int colA = (g8 >> 1) << 3;
    const int rowB = within + ((g8 >> 1) << 3);
    const int colB = (g8 & 1) << 3;

    uint32_t aQ[8][4];
    {
        uint32_t qa = s2u(&Ks[(warp * 16 + rowA) * kStride + colA]);
        #pragma unroll
        for (int kt = 0; kt < 8; ++kt)
            ldsm4(qa + kt * 32, aQ[kt][0], aQ[kt][1], aQ[kt][2], aQ[kt][3]);
    }
    __syncthreads();

    float accO[16][4];
    #pragma unroll
    for (int i = 0; i < 16; ++i)
        accO[i][0] = accO[i][1] = accO[i][2] = accO[i][3] = 0.f;
    float m0 = -1e30f, m1 = -1e30f, l0 = 0.f, l1 = 0.f;

    const uint32_t kaBase = s2u(&Ks[rowB * kStride + colB]);
    const uint32_t vaBase = s2u(&Vs[rowA * kStride + colA]);

    const size_t kvHead = (size_t)(b * kHKV + hkv) * kMAXB;
    const int nblocks = (n + kBS - 1) / kBS;

    for (int j = 0; j < nblocks; ++j) {
        const int pb = bt[b * kNB + j];
        const float* kPtr = sk + (kvHead + pb) * (size_t)(kBS * kD);
        const float* vPtr = sv + (kvHead + pb) * (size_t)(kBS * kD);
        {
            const int r = tid >> 1, c = (tid & 1) * 64;
            #pragma unroll
            for (int i = 0; i < 16; ++i) {
                float4 f = *reinterpret_cast<const float4*>(kPtr + r * kD + c + i * 4);
                *reinterpret_cast<uint2*>(&Ks[r * kStride + c + i * 4]) =
                    make_uint2(packh2(f.x, f.y), packh2(f.z, f.w));
            }
            #pragma unroll
            for (int i = 0; i < 16; ++i) {
                float4 f = *reinterpret_cast<const float4*>(vPtr + r * kD + c + i * 4);
                *reinterpret_cast<uint2*>(&Vs[r * kStride + c + i * 4]) =
                    make_uint2(packh2(f.x, f.y), packh2(f.z, f.w));
            }
        }
        __syncthreads();

        // ---- S = Q K^T  (16 q-rows per warp x 128 kv cols) ----
        float accS[16][4];
        #pragma unroll
        for (int i = 0; i < 16; ++i)
            accS[i][0] = accS[i][1] = accS[i][2] = accS[i][3] = 0.f;

        #pragma unroll
        for (int ntp = 0; ntp < 8; ++ntp) {
            #pragma unroll
            for (int kt = 0; kt < 8; ++kt) {
                uint32_t b0, b1, b2, b3;
                ldsm4(kaBase + (uint32_t)(ntp * 16 * kStride + kt * 16) * 2,
                      b0, b1, b2, b3);
                mma16816(accS[2 * ntp],     aQ[kt][0], aQ[kt][1], aQ[kt][2], aQ[kt][3], b0, b1);
                mma16816(accS[2 * ntp + 1], aQ[kt][0], aQ[kt][1], aQ[kt][2], aQ[kt][3], b2, b3);
            }
        }

        // ---- mask the tail block ----
        const int valid = n - j * kBS;
        if (valid < kBS) {
            const int cbm = 2 * (lane & 3);
            #pragma unroll
            for (int nt = 0; nt < 16; ++nt) {
                int c = nt * 8 + cbm;
                if (c >= valid)     { accS[nt][0] = -1e30f; accS[nt][2] = -1e30f; }
                if (c + 1 >= valid) { accS[nt][1] = -1e30f; accS[nt][3] = -1e30f; }
            }
        }

        // ---- online softmax ----
        float mb0 = m0, mb1 = m1;
        #pragma unroll
        for (int nt = 0; nt < 16; ++nt) {
            mb0 = fmaxf(mb0, fmaxf(accS[nt][0], accS[nt][1]));
            mb1 = fmaxf(mb1, fmaxf(accS[nt][2], accS[nt][3]));
        }
        mb0 = fmaxf(mb0, __shfl_xor_sync(0xffffffffu, mb0, 1));
        mb0 = fmaxf(mb0, __shfl_xor_sync(0xffffffffu, mb0, 2));
        mb1 = fmaxf(mb1, __shfl_xor_sync(0xffffffffu, mb1, 1));
        mb1 = fmaxf(mb1, __shfl_xor_sync(0xffffffffu, mb1, 2));

        const float al0 = fexp2((m0 - mb0) * kCexp);
        const float al1 = fexp2((m1 - mb1) * kCexp);
        m0 = mb0; m1 = mb1;
        l0 *= al0; l1 *= al1;
        #pragma unroll
        for (int nt = 0; nt < 16; ++nt) {
            accO[nt][0] *= al0; accO[nt][1] *= al0;
            accO[nt][2] *= al1; accO[nt][3] *= al1;
        }

        // ---- P = exp(S - m); O += P V ; P accum frags become A frags ----
        float rs0 = 0.f, rs1 = 0.f;
        #pragma unroll
        for (int kk = 0; kk < 8; ++kk) {
            float p00 = fexp2((accS[2 * kk][0] - mb0) * kCexp);
            float p01 = fexp2((accS[2 * kk][1] - mb0) * kCexp);
            float p02 = fexp2((accS[2 * kk][2] - mb1) * kCexp);
            float p03 = fexp2((accS[2 * kk][3] - mb1) * kCexp);
            float p10 = fexp2((accS[2 * kk + 1][0] - mb0) * kCexp);
            float p11 = fexp2((accS[2 * kk + 1][1] - mb0) * kCexp);
            float p12 = fexp2((accS[2 * kk + 1][2] - mb1) * kCexp);
            float p13 = fexp2((accS[2 * kk + 1][3] - mb1) * kCexp);
            rs0 += (p00 + p01) + (p10 + p11);
            rs1 += (p02 + p03) + (p12 + p13);
            uint32_t a0 = packh2(p00, p01), a1 = packh2(p02, p03);
            uint32_t a2 = packh2(p10, p11), a3 = packh2(p12, p13);
            #pragma unroll
            for (int ntp = 0; ntp < 8; ++ntp) {
                uint32_t b0, b1, b2, b3;
                ldsm4t(vaBase + (uint32_t)(kk * 16 * kStride + ntp * 16) * 2,
                       b0, b1, b2, b3);
                mma16816(accO[2 * ntp],     a0, a1, a2, a3, b0, b1);
                mma16816(accO[2 * ntp + 1], a0, a1, a2, a3, b2, b3);
            }
        }
        rs0 += __shfl_xor_sync(0xffffffffu, rs0, 1);
        rs0 += __shfl_xor_sync(0xffffffffu, rs0, 2);
        rs1 += __shfl_xor_sync(0xffffffffu, rs1, 1);
        rs1 += __shfl_xor_sync(0xffffffffu, rs1, 2);
        l0 += rs0; l1 += rs1;

        __syncthreads();   // protect K/V tiles before next block's loads
    }

    // ---- epilogue: O / l ----
    const float inv0 = 1.0f / l0;
    const float inv1 = 1.0f / l1;
    const int t0 = warp * 16 + (lane >> 2);
    const int cb = 2 * (lane & 3);
    #pragma unroll
    for (int nt = 0; nt < 16; ++nt) {
        int c = nt * 8 + cb;
        *reinterpret_cast<float2*>(outBase + t0 * kD + c) =
            make_float2(accO[nt][0] * inv0, accO[nt][1] * inv0);
        *reinterpret_cast<float2*>(outBase + (t0 + 8) * kD + c) =
            make_float2(accO[nt][2] * inv1, accO[nt][3] * inv1);
    }
}

} // namespace

extern "C" void kernel_launch(void* const* d_in, const int* in_sizes, int n_in,
                              void* d_out, int out_size) {
    const float* q  = (const float*)d_in[0];
    const float* sk = (const float*)d_in[1];
    const float* sv = (const float*)d_in[2];
    const int*   bt = (const int*)d_in[3];
    const int*   cl = (const int*)d_in[4];
    float* out = (float*)d_out;

    cudaFuncSetAttribute(attn_kernel,
                         cudaFuncAttributeMaxDynamicSharedMemorySize, kSmemBytes);
    dim3 grid(kHQ, kB);
    attn_kernel<<<grid, 256, kSmemBytes>>>(q, sk, sv, bt, cl, out);
}